// round 14
// baseline (speedup 1.0000x reference)
#include <cuda_runtime.h>

// PeripheralDWConv2d, fully fused FFT kernel (512 threads/CTA):
//  one CTA per packed image (z = x[2k] + i*x[2k+1]):
//   1. 128-pt register/shuffle DIF FFT along x, 2 rows interleaved per step
//      -> transposed smem planes Xr/Xi[f][s] (s = y+25, zero halo)
//   2. 51-tap conv along y per frequency slot (16-y register window,
//      weight prefetch)
//   3. register/shuffle DIT inverse FFT (2 rows interleaved), crop, unpack.

#define KSZ 51
#define PP  13
#define RAD 25
#define NCH 128
#define WROW 52
#define NBIN 128
#define NPIMG 1024          // 8 batch-pairs * 128 channels
#define YDIM 64
#define SROW 115            // padded y-stride (odd -> conflict-free)
#define NTHR 512

__device__ float  g_wpad[NCH * KSZ * WROW];
__device__ float2 g_twtab[128];                     // exp(-2*pi*i*k/128)
__device__ float2 g_wf[NCH * KSZ * NBIN];           // conj spectra, bitrev slots

__constant__ int c_qpos[26] = {0,1,2,2,3,3,3,3,4,4,4,4,4,4,4,4,
                               5,5,5,5,5,5,5,5,5,6};

__global__ void build_weights_kernel(const float* __restrict__ wc,
                                     const float* __restrict__ kpe) {
    int t = blockIdx.x * blockDim.x + threadIdx.x;
    const int total = NCH * KSZ * WROW;
    if (t >= total) return;
    int c  = t / (KSZ * WROW);
    int r  = t - c * (KSZ * WROW);
    int dy = r / WROW;
    int dx = r - dy * WROW;
    float v = 0.f;
    if (dx < KSZ) {
        int oi = dy - RAD; int ai = oi < 0 ? -oi : oi;
        int ii = 6 + (oi < 0 ? -c_qpos[ai] : c_qpos[ai]);
        int oj = dx - RAD; int aj = oj < 0 ? -oj : oj;
        int jj = 6 + (oj < 0 ? -c_qpos[aj] : c_qpos[aj]);
        v = wc[c * (PP * PP) + ii * PP + jj] + kpe[dy * KSZ + dx];
    }
    g_wpad[t] = v;
}

__global__ void init_tw_kernel() {
    int k = threadIdx.x;
    if (k < 128) {
        float s, c;
        sincospif(-(float)k / 64.0f, &s, &c);
        g_twtab[k] = make_float2(c, s);
    }
}

__device__ __forceinline__ float2 cmulf(float2 a, float2 b) {
    return make_float2(a.x * b.x - a.y * b.y, a.x * b.y + a.y * b.x);
}
__device__ __forceinline__ float2 cmulc(float2 a, float2 b) {  // a * conj(b)
    return make_float2(a.x * b.x + a.y * b.y, a.y * b.x - a.x * b.y);
}

__device__ __forceinline__ void load_tw(float2 tw[7], int t) {
    tw[0] = g_twtab[t];                // d=64, pair a
    tw[1] = g_twtab[t + 32];           // d=64, pair b
    tw[2] = g_twtab[2 * t];            // d=32
    tw[3] = g_twtab[(t & 15) * 4];     // d=16
    tw[4] = g_twtab[(t & 7) * 8];      // d=8
    tw[5] = g_twtab[(t & 3) * 16];     // d=4
    tw[6] = g_twtab[(t & 1) * 32];     // d=2
}

// Forward 128-pt DIF. Thread t holds elems t,t+32,t+64,t+96.
// Output slot p = bin bitrev7(p).
__device__ __forceinline__ void fft128_fwd(float2 z[4], int t, const float2 tw[7]) {
    {   // d=64
        float2 a, b;
        a = z[0]; b = z[2];
        z[0] = make_float2(a.x + b.x, a.y + b.y);
        z[2] = cmulf(make_float2(a.x - b.x, a.y - b.y), tw[0]);
        a = z[1]; b = z[3];
        z[1] = make_float2(a.x + b.x, a.y + b.y);
        z[3] = cmulf(make_float2(a.x - b.x, a.y - b.y), tw[1]);
    }
    {   // d=32
        float2 a, b;
        a = z[0]; b = z[1];
        z[0] = make_float2(a.x + b.x, a.y + b.y);
        z[1] = cmulf(make_float2(a.x - b.x, a.y - b.y), tw[2]);
        a = z[2]; b = z[3];
        z[2] = make_float2(a.x + b.x, a.y + b.y);
        z[3] = cmulf(make_float2(a.x - b.x, a.y - b.y), tw[2]);
    }
#pragma unroll
    for (int s = 0; s < 5; ++s) {      // d = 16,8,4,2,1
        int d = 16 >> s;
        float2 w = (s < 4) ? tw[3 + s] : make_float2(1.f, 0.f);
        bool hi = (t & d) != 0;
#pragma unroll
        for (int j = 0; j < 4; ++j) {
            float ox = __shfl_xor_sync(0xffffffffu, z[j].x, d);
            float oy = __shfl_xor_sync(0xffffffffu, z[j].y, d);
            if (hi) {
                float2 df = make_float2(ox - z[j].x, oy - z[j].y);
                z[j] = (d == 1) ? df : cmulf(df, w);
            } else {
                z[j] = make_float2(z[j].x + ox, z[j].y + oy);
            }
        }
    }
}

// Inverse 128-pt DIT (unnormalized). Input slot p = bin bitrev7(p); natural out.
__device__ __forceinline__ void fft128_inv(float2 z[4], int t, const float2 tw[7]) {
#pragma unroll
    for (int s = 0; s < 5; ++s) {      // d = 1,2,4,8,16
        int d = 1 << s;
        float2 w = (s > 0) ? tw[7 - s] : make_float2(1.f, 0.f);  // tw[6..3]
        bool hi = (t & d) != 0;
#pragma unroll
        for (int j = 0; j < 4; ++j) {
            float ox = __shfl_xor_sync(0xffffffffu, z[j].x, d);
            float oy = __shfl_xor_sync(0xffffffffu, z[j].y, d);
            if (hi) {
                float2 vm = (d == 1) ? z[j] : cmulc(z[j], w);
                z[j] = make_float2(ox - vm.x, oy - vm.y);
            } else {
                float2 vo = (d == 1) ? make_float2(ox, oy)
                                     : cmulc(make_float2(ox, oy), w);
                z[j] = make_float2(z[j].x + vo.x, z[j].y + vo.y);
            }
        }
    }
    {   // len=64 local: w = conj(tw[2])
        float2 u, v;
        v = cmulc(z[1], tw[2]); u = z[0];
        z[0] = make_float2(u.x + v.x, u.y + v.y);
        z[1] = make_float2(u.x - v.x, u.y - v.y);
        v = cmulc(z[3], tw[2]); u = z[2];
        z[2] = make_float2(u.x + v.x, u.y + v.y);
        z[3] = make_float2(u.x - v.x, u.y - v.y);
    }
    {   // len=128 local: conj(tw[0]), conj(tw[1])
        float2 u, v;
        v = cmulc(z[2], tw[0]); u = z[0];
        z[0] = make_float2(u.x + v.x, u.y + v.y);
        z[2] = make_float2(u.x - v.x, u.y - v.y);
        v = cmulc(z[3], tw[1]); u = z[1];
        z[1] = make_float2(u.x + v.x, u.y + v.y);
        z[3] = make_float2(u.x - v.x, u.y - v.y);
    }
}

__global__ __launch_bounds__(256) void fft_w_kernel() {
    int t = threadIdx.x & 31, w = threadIdx.x >> 5;
    float2 tw[7]; load_tw(tw, t);
    int row = blockIdx.x * 8 + w;                 // c*51+dy, < 6528
    const float* src = g_wpad + row * WROW;
    float2 z[4];
    z[0] = make_float2(src[t], 0.f);
    z[1] = make_float2((t + 32) < KSZ ? src[t + 32] : 0.f, 0.f);
    z[2] = make_float2(0.f, 0.f);
    z[3] = make_float2(0.f, 0.f);
    fft128_fwd(z, t, tw);
    float2* dst = g_wf + (size_t)row * NBIN;
    dst[t]      = make_float2(z[0].x, -z[0].y);
    dst[t + 32] = make_float2(z[1].x, -z[1].y);
    dst[t + 64] = make_float2(z[2].x, -z[2].y);
    dst[t + 96] = make_float2(z[3].x, -z[3].y);
}

// Fully fused: fwd FFT -> transposed smem -> y-conv -> inverse FFT -> out.
// One CTA per packed image, 512 threads, paired-row FFTs for ILP.
__global__ __launch_bounds__(NTHR, 1)
void conv_mono_kernel(const float* __restrict__ x, float* __restrict__ out) {
    extern __shared__ float smf[];
    float*  Xr = smf;                         // 128 * SROW
    float*  Xi = Xr + NBIN * SROW;            // 128 * SROW
    float2* WS = (float2*)(Xi + NBIN * SROW); // 64*128 float2: weights, then S

    const int pimg = blockIdx.x;
    const int pb   = pimg >> 7;
    const int c    = pimg & 127;
    const int tid  = threadIdx.x;
    const int t    = tid & 31;                // lane
    const int w    = tid >> 5;                // warp 0..15

    float2 tw[7]; load_tw(tw, t);

    // phase 0: zero halo only (s in [0,25) u [89,115)) + stage weights
    for (int i = tid; i < NBIN * 51; i += NTHR) {
        int f = i / 51, j = i - f * 51;
        int s = (j < 25) ? j : (64 + j);      // 89..114
        Xr[f * SROW + s] = 0.f;
        Xi[f * SROW + s] = 0.f;
    }
    {
        const float2* wsrc = g_wf + (size_t)c * (KSZ * NBIN);
        for (int i = tid; i < KSZ * NBIN; i += NTHR) WS[i] = wsrc[i];
    }
    __syncthreads();

    // phase 1: fwd FFT 4 rows per warp, 2 interleaved at a time
    const float* img0 = x + (((size_t)(2 * pb)     * NCH + c) * 64) * 64;
    const float* img1 = x + (((size_t)(2 * pb + 1) * NCH + c) * 64) * 64;
#pragma unroll
    for (int rp = 0; rp < 2; ++rp) {
        int ya = w * 4 + rp * 2;
        int yb = ya + 1;
        const float* a0 = img0 + ya * 64;
        const float* a1 = img1 + ya * 64;
        const float* b0 = img0 + yb * 64;
        const float* b1 = img1 + yb * 64;
        float2 za[4], zb[4];
        za[0] = make_float2(a0[t],      a1[t]);
        za[1] = make_float2(a0[t + 32], a1[t + 32]);
        za[2] = make_float2(0.f, 0.f);
        za[3] = make_float2(0.f, 0.f);
        zb[0] = make_float2(b0[t],      b1[t]);
        zb[1] = make_float2(b0[t + 32], b1[t + 32]);
        zb[2] = make_float2(0.f, 0.f);
        zb[3] = make_float2(0.f, 0.f);
        fft128_fwd(za, t, tw);            // independent chains -> ptxas
        fft128_fwd(zb, t, tw);            // interleaves them
        int sa = ya + RAD, sb = yb + RAD;
#pragma unroll
        for (int j = 0; j < 4; ++j) {
            Xr[(t + 32 * j) * SROW + sa] = za[j].x;
            Xi[(t + 32 * j) * SROW + sa] = za[j].y;
            Xr[(t + 32 * j) * SROW + sb] = zb[j].x;
            Xi[(t + 32 * j) * SROW + sb] = zb[j].y;
        }
    }
    __syncthreads();

    // phase 2: y-conv. task = (bin f, 16-consecutive-y block)
    const int f  = tid & 127;
    const int y0 = (tid >> 7) * 16;           // 0,16,32,48
    float ar[16], ai[16];
    {
        const float*  xr = Xr + f * SROW + y0;
        const float*  xi = Xi + f * SROW + y0;
        const float2* wp = WS + f;

        float win_r[16], win_i[16];
#pragma unroll
        for (int i = 0; i < 16; ++i) { ar[i] = 0.f; ai[i] = 0.f; }
#pragma unroll
        for (int j = 0; j < 15; ++j) { win_r[j] = xr[j]; win_i[j] = xi[j]; }
        float2 wv = wp[0];

#pragma unroll
        for (int dy = 0; dy < KSZ; ++dy) {
            win_r[(dy + 15) & 15] = xr[dy + 15];   // max s = 48+65 = 113 < 115
            win_i[(dy + 15) & 15] = xi[dy + 15];
            float2 nw = (dy < KSZ - 1) ? wp[(dy + 1) * NBIN] : wv;  // prefetch
#pragma unroll
            for (int i = 0; i < 16; ++i) {
                float xrv = win_r[(dy + i) & 15];
                float xiv = win_i[(dy + i) & 15];
                ar[i] = fmaf(xrv, wv.x, fmaf(-xiv, wv.y, ar[i]));
                ai[i] = fmaf(xrv, wv.y, fmaf( xiv, wv.x, ai[i]));
            }
            wv = nw;
        }
    }
    __syncthreads();   // all weight reads done; WS becomes S

    // phase 3: store S[y][f]
#pragma unroll
    for (int i = 0; i < 16; ++i)
        WS[(y0 + i) * NBIN + f] = make_float2(ar[i], ai[i]);
    __syncthreads();

    // phase 4: inverse FFT 4 rows per warp, 2 interleaved; crop, unpack, write
    float* o0 = out + (((size_t)(2 * pb)     * NCH + c) * 64) * 64;
    float* o1 = out + (((size_t)(2 * pb + 1) * NCH + c) * 64) * 64;
    const float scl = 1.0f / 128.0f;
#pragma unroll
    for (int rp = 0; rp < 2; ++rp) {
        int ya = w * 4 + rp * 2;
        int yb = ya + 1;
        const float2* Sa = WS + ya * NBIN;
        const float2* Sb = WS + yb * NBIN;
        float2 za[4], zb[4];
        za[0] = Sa[t]; za[1] = Sa[t + 32]; za[2] = Sa[t + 64]; za[3] = Sa[t + 96];
        zb[0] = Sb[t]; zb[1] = Sb[t + 32]; zb[2] = Sb[t + 64]; zb[3] = Sb[t + 96];
        fft128_inv(za, t, tw);
        fft128_inv(zb, t, tw);
        float* pa0 = o0 + ya * 64;
        float* pa1 = o1 + ya * 64;
        float* pb0 = o0 + yb * 64;
        float* pb1 = o1 + yb * 64;
        pa0[t + 25] = za[0].x * scl;
        pa1[t + 25] = za[0].y * scl;
        pb0[t + 25] = zb[0].x * scl;
        pb1[t + 25] = zb[0].y * scl;
        if (t < 7) {
            pa0[t + 57] = za[1].x * scl;
            pa1[t + 57] = za[1].y * scl;
            pb0[t + 57] = zb[1].x * scl;
            pb1[t + 57] = zb[1].y * scl;
        } else {
            pa0[t - 7] = za[3].x * scl;
            pa1[t - 7] = za[3].y * scl;
            pb0[t - 7] = zb[3].x * scl;
            pb1[t - 7] = zb[3].y * scl;
        }
    }
}

extern "C" void kernel_launch(void* const* d_in, const int* in_sizes, int n_in,
                              void* d_out, int out_size) {
    const float* x   = (const float*)d_in[0];   // 16*128*64*64
    const float* wc  = (const float*)d_in[1];   // 128*169
    const float* kpe = (const float*)d_in[2];   // 51*51
    float* out = (float*)d_out;

    init_tw_kernel<<<1, 128>>>();

    const int total_w = NCH * KSZ * WROW;
    build_weights_kernel<<<(total_w + 255) / 256, 256>>>(wc, kpe);

    fft_w_kernel<<<(NCH * KSZ) / 8, 256>>>();        // 6528 rows

    const size_t msmem = (size_t)(2 * NBIN * SROW) * sizeof(float)
                       + (size_t)(YDIM * NBIN) * sizeof(float2);   // 183296 B
    cudaFuncSetAttribute(conv_mono_kernel,
                         cudaFuncAttributeMaxDynamicSharedMemorySize, (int)msmem);
    conv_mono_kernel<<<NPIMG, NTHR, msmem>>>(x, out);
}

// round 15
// speedup vs baseline: 1.6714x; 1.6714x over previous
#include <cuda_runtime.h>
#include <cuda_pipeline.h>

// PeripheralDWConv2d, fused FFT kernel, persistent CTAs:
//  grid=148, each CTA loops over ~7 packed images (z = x[2k] + i*x[2k+1]):
//   1. 128-pt register/shuffle DIF FFT along x (inputs prefetched to regs)
//      -> transposed smem planes Xr/Xi[f][s]  (halo zeroed once)
//   2. 51-tap conv along y per frequency slot (16-y register window);
//      next image's inputs prefetched under the FMA stream
//   3. register/shuffle DIT inverse FFT per row, crop, unpack, store.

#define KSZ 51
#define PP  13
#define RAD 25
#define NCH 128
#define WROW 52
#define NBIN 128
#define NPIMG 1024          // 8 batch-pairs * 128 channels
#define YDIM 64
#define SROW 115            // padded y-stride (odd -> conflict-free)
#define NTHR 512
#define NCTA 148

__device__ float  g_wpad[NCH * KSZ * WROW];
__device__ float2 g_twtab[128];                     // exp(-2*pi*i*k/128)
__device__ float2 g_wf[NCH * KSZ * NBIN];           // conj spectra, bitrev slots

__constant__ int c_qpos[26] = {0,1,2,2,3,3,3,3,4,4,4,4,4,4,4,4,
                               5,5,5,5,5,5,5,5,5,6};

__global__ void build_weights_kernel(const float* __restrict__ wc,
                                     const float* __restrict__ kpe) {
    int t = blockIdx.x * blockDim.x + threadIdx.x;
    const int total = NCH * KSZ * WROW;
    if (t >= total) return;
    int c  = t / (KSZ * WROW);
    int r  = t - c * (KSZ * WROW);
    int dy = r / WROW;
    int dx = r - dy * WROW;
    float v = 0.f;
    if (dx < KSZ) {
        int oi = dy - RAD; int ai = oi < 0 ? -oi : oi;
        int ii = 6 + (oi < 0 ? -c_qpos[ai] : c_qpos[ai]);
        int oj = dx - RAD; int aj = oj < 0 ? -oj : oj;
        int jj = 6 + (oj < 0 ? -c_qpos[aj] : c_qpos[aj]);
        v = wc[c * (PP * PP) + ii * PP + jj] + kpe[dy * KSZ + dx];
    }
    g_wpad[t] = v;
}

__global__ void init_tw_kernel() {
    int k = threadIdx.x;
    if (k < 128) {
        float s, c;
        sincospif(-(float)k / 64.0f, &s, &c);
        g_twtab[k] = make_float2(c, s);
    }
}

__device__ __forceinline__ float2 cmulf(float2 a, float2 b) {
    return make_float2(a.x * b.x - a.y * b.y, a.x * b.y + a.y * b.x);
}
__device__ __forceinline__ float2 cmulc(float2 a, float2 b) {  // a * conj(b)
    return make_float2(a.x * b.x + a.y * b.y, a.y * b.x - a.x * b.y);
}

__device__ __forceinline__ void load_tw(float2 tw[7], int t) {
    tw[0] = g_twtab[t];                // d=64, pair a
    tw[1] = g_twtab[t + 32];           // d=64, pair b
    tw[2] = g_twtab[2 * t];            // d=32
    tw[3] = g_twtab[(t & 15) * 4];     // d=16
    tw[4] = g_twtab[(t & 7) * 8];      // d=8
    tw[5] = g_twtab[(t & 3) * 16];     // d=4
    tw[6] = g_twtab[(t & 1) * 32];     // d=2
}

// Forward 128-pt DIF. Thread t holds elems t,t+32,t+64,t+96.
// Output slot p = bin bitrev7(p).
__device__ __forceinline__ void fft128_fwd(float2 z[4], int t, const float2 tw[7]) {
    {   // d=64
        float2 a, b;
        a = z[0]; b = z[2];
        z[0] = make_float2(a.x + b.x, a.y + b.y);
        z[2] = cmulf(make_float2(a.x - b.x, a.y - b.y), tw[0]);
        a = z[1]; b = z[3];
        z[1] = make_float2(a.x + b.x, a.y + b.y);
        z[3] = cmulf(make_float2(a.x - b.x, a.y - b.y), tw[1]);
    }
    {   // d=32
        float2 a, b;
        a = z[0]; b = z[1];
        z[0] = make_float2(a.x + b.x, a.y + b.y);
        z[1] = cmulf(make_float2(a.x - b.x, a.y - b.y), tw[2]);
        a = z[2]; b = z[3];
        z[2] = make_float2(a.x + b.x, a.y + b.y);
        z[3] = cmulf(make_float2(a.x - b.x, a.y - b.y), tw[2]);
    }
#pragma unroll
    for (int s = 0; s < 5; ++s) {      // d = 16,8,4,2,1
        int d = 16 >> s;
        float2 w = (s < 4) ? tw[3 + s] : make_float2(1.f, 0.f);
        bool hi = (t & d) != 0;
#pragma unroll
        for (int j = 0; j < 4; ++j) {
            float ox = __shfl_xor_sync(0xffffffffu, z[j].x, d);
            float oy = __shfl_xor_sync(0xffffffffu, z[j].y, d);
            if (hi) {
                float2 df = make_float2(ox - z[j].x, oy - z[j].y);
                z[j] = (d == 1) ? df : cmulf(df, w);
            } else {
                z[j] = make_float2(z[j].x + ox, z[j].y + oy);
            }
        }
    }
}

// Inverse 128-pt DIT (unnormalized). Input slot p = bin bitrev7(p); natural out.
__device__ __forceinline__ void fft128_inv(float2 z[4], int t, const float2 tw[7]) {
#pragma unroll
    for (int s = 0; s < 5; ++s) {      // d = 1,2,4,8,16
        int d = 1 << s;
        float2 w = (s > 0) ? tw[7 - s] : make_float2(1.f, 0.f);  // tw[6..3]
        bool hi = (t & d) != 0;
#pragma unroll
        for (int j = 0; j < 4; ++j) {
            float ox = __shfl_xor_sync(0xffffffffu, z[j].x, d);
            float oy = __shfl_xor_sync(0xffffffffu, z[j].y, d);
            if (hi) {
                float2 vm = (d == 1) ? z[j] : cmulc(z[j], w);
                z[j] = make_float2(ox - vm.x, oy - vm.y);
            } else {
                float2 vo = (d == 1) ? make_float2(ox, oy)
                                     : cmulc(make_float2(ox, oy), w);
                z[j] = make_float2(z[j].x + vo.x, z[j].y + vo.y);
            }
        }
    }
    {   // len=64 local: w = conj(tw[2])
        float2 u, v;
        v = cmulc(z[1], tw[2]); u = z[0];
        z[0] = make_float2(u.x + v.x, u.y + v.y);
        z[1] = make_float2(u.x - v.x, u.y - v.y);
        v = cmulc(z[3], tw[2]); u = z[2];
        z[2] = make_float2(u.x + v.x, u.y + v.y);
        z[3] = make_float2(u.x - v.x, u.y - v.y);
    }
    {   // len=128 local: conj(tw[0]), conj(tw[1])
        float2 u, v;
        v = cmulc(z[2], tw[0]); u = z[0];
        z[0] = make_float2(u.x + v.x, u.y + v.y);
        z[2] = make_float2(u.x - v.x, u.y - v.y);
        v = cmulc(z[3], tw[1]); u = z[1];
        z[1] = make_float2(u.x + v.x, u.y + v.y);
        z[3] = make_float2(u.x - v.x, u.y - v.y);
    }
}

__global__ __launch_bounds__(256) void fft_w_kernel() {
    int t = threadIdx.x & 31, w = threadIdx.x >> 5;
    float2 tw[7]; load_tw(tw, t);
    int row = blockIdx.x * 8 + w;                 // c*51+dy, < 6528
    const float* src = g_wpad + row * WROW;
    float2 z[4];
    z[0] = make_float2(src[t], 0.f);
    z[1] = make_float2((t + 32) < KSZ ? src[t + 32] : 0.f, 0.f);
    z[2] = make_float2(0.f, 0.f);
    z[3] = make_float2(0.f, 0.f);
    fft128_fwd(z, t, tw);
    float2* dst = g_wf + (size_t)row * NBIN;
    dst[t]      = make_float2(z[0].x, -z[0].y);
    dst[t + 32] = make_float2(z[1].x, -z[1].y);
    dst[t + 64] = make_float2(z[2].x, -z[2].y);
    dst[t + 96] = make_float2(z[3].x, -z[3].y);
}

// Prefetch one packed image's per-thread FFT inputs (16 floats) to registers.
__device__ __forceinline__ void prefetch_img(float pf[16], const float* __restrict__ x,
                                             int pimg, int t, int w) {
    int pb = pimg >> 7, c = pimg & 127;
    const float* i0 = x + (((size_t)(2 * pb)     * NCH + c) << 12);
    const float* i1 = x + (((size_t)(2 * pb + 1) * NCH + c) << 12);
#pragma unroll
    for (int r = 0; r < 4; ++r) {
        int y = w * 4 + r;
        pf[r * 4 + 0] = i0[y * 64 + t];
        pf[r * 4 + 1] = i0[y * 64 + t + 32];
        pf[r * 4 + 2] = i1[y * 64 + t];
        pf[r * 4 + 3] = i1[y * 64 + t + 32];
    }
}

// Persistent fused kernel: grid = NCTA, each CTA loops images b, b+148, ...
__global__ __launch_bounds__(NTHR, 1)
void conv_persist_kernel(const float* __restrict__ x, float* __restrict__ out) {
    extern __shared__ float smf[];
    float*  Xr = smf;                         // 128 * SROW
    float*  Xi = Xr + NBIN * SROW;            // 128 * SROW
    float2* WS = (float2*)(Xi + NBIN * SROW); // 64*128 float2: weights, then S

    const int tid = threadIdx.x;
    const int t   = tid & 31;                 // lane
    const int w   = tid >> 5;                 // warp 0..15

    float2 tw[7]; load_tw(tw, t);

    // one-time halo zero: s in [0,25) u [89,115). Phase 1 rewrites s in
    // [25,89) densely each image, so the halo stays valid forever.
    for (int i = tid; i < NBIN * 51; i += NTHR) {
        int f = i / 51, j = i - f * 51;
        int s = (j < 25) ? j : (64 + j);      // 89..114
        Xr[f * SROW + s] = 0.f;
        Xi[f * SROW + s] = 0.f;
    }

    int pimg = blockIdx.x;
    float pf[16];
    if (pimg < NPIMG) prefetch_img(pf, x, pimg, t, w);

    while (pimg < NPIMG) {
        const int pb = pimg >> 7;
        const int c  = pimg & 127;

        // stage weights via cp.async (latency hidden under phase 1)
        {
            const float2* wsrc = g_wf + (size_t)c * (KSZ * NBIN);
            for (int i = tid; i < KSZ * NBIN; i += NTHR)
                __pipeline_memcpy_async(&WS[i], &wsrc[i], sizeof(float2));
            __pipeline_commit();
        }

        // phase 1: fwd FFT 4 rows per warp from prefetched regs, scatter
#pragma unroll
        for (int r = 0; r < 4; ++r) {
            int y = w * 4 + r;                // 0..63
            float2 z[4];
            z[0] = make_float2(pf[r * 4 + 0], pf[r * 4 + 2]);
            z[1] = make_float2(pf[r * 4 + 1], pf[r * 4 + 3]);
            z[2] = make_float2(0.f, 0.f);
            z[3] = make_float2(0.f, 0.f);
            fft128_fwd(z, t, tw);
            int s = y + RAD;
#pragma unroll
            for (int j = 0; j < 4; ++j) {
                Xr[(t + 32 * j) * SROW + s] = z[j].x;
                Xi[(t + 32 * j) * SROW + s] = z[j].y;
            }
        }
        __pipeline_wait_prior(0);
        __syncthreads();                       // X + W ready

        // phase 2: prefetch next image, then y-conv
        const int pnext = pimg + NCTA;
        if (pnext < NPIMG) prefetch_img(pf, x, pnext, t, w);

        const int f  = tid & 127;
        const int y0 = (tid >> 7) * 16;        // 0,16,32,48
        float ar[16], ai[16];
        {
            const float*  xr = Xr + f * SROW + y0;
            const float*  xi = Xi + f * SROW + y0;
            const float2* wp = WS + f;

            float win_r[16], win_i[16];
#pragma unroll
            for (int i = 0; i < 16; ++i) { ar[i] = 0.f; ai[i] = 0.f; }
#pragma unroll
            for (int j = 0; j < 15; ++j) { win_r[j] = xr[j]; win_i[j] = xi[j]; }

#pragma unroll
            for (int dy = 0; dy < KSZ; ++dy) {
                win_r[(dy + 15) & 15] = xr[dy + 15];   // max s = 113 < 115
                win_i[(dy + 15) & 15] = xi[dy + 15];
                float2 wv = wp[dy * NBIN];
#pragma unroll
                for (int i = 0; i < 16; ++i) {
                    float xrv = win_r[(dy + i) & 15];
                    float xiv = win_i[(dy + i) & 15];
                    ar[i] = fmaf(xrv, wv.x, fmaf(-xiv, wv.y, ar[i]));
                    ai[i] = fmaf(xrv, wv.y, fmaf( xiv, wv.x, ai[i]));
                }
            }
        }
        __syncthreads();   // all weight reads done; WS becomes S

        // phase 3: store S[y][f]
#pragma unroll
        for (int i = 0; i < 16; ++i)
            WS[(y0 + i) * NBIN + f] = make_float2(ar[i], ai[i]);
        __syncthreads();

        // phase 4: inverse FFT 4 rows per warp, crop, unpack, write out
        float* o0 = out + (((size_t)(2 * pb)     * NCH + c) << 12);
        float* o1 = out + (((size_t)(2 * pb + 1) * NCH + c) << 12);
        const float scl = 1.0f / 128.0f;
#pragma unroll
        for (int r = 0; r < 4; ++r) {
            int y = w * 4 + r;
            const float2* S = WS + y * NBIN;
            float2 z[4];
            z[0] = S[t];
            z[1] = S[t + 32];
            z[2] = S[t + 64];
            z[3] = S[t + 96];
            fft128_inv(z, t, tw);
            float* p0 = o0 + y * 64;
            float* p1 = o1 + y * 64;
            p0[t + 25] = z[0].x * scl;
            p1[t + 25] = z[0].y * scl;
            if (t < 7) {
                p0[t + 57] = z[1].x * scl;
                p1[t + 57] = z[1].y * scl;
            } else {
                p0[t - 7] = z[3].x * scl;
                p1[t - 7] = z[3].y * scl;
            }
        }
        __syncthreads();   // S reads done before next image's W staging

        pimg = pnext;
    }
}

extern "C" void kernel_launch(void* const* d_in, const int* in_sizes, int n_in,
                              void* d_out, int out_size) {
    const float* x   = (const float*)d_in[0];   // 16*128*64*64
    const float* wc  = (const float*)d_in[1];   // 128*169
    const float* kpe = (const float*)d_in[2];   // 51*51
    float* out = (float*)d_out;

    init_tw_kernel<<<1, 128>>>();

    const int total_w = NCH * KSZ * WROW;
    build_weights_kernel<<<(total_w + 255) / 256, 256>>>(wc, kpe);

    fft_w_kernel<<<(NCH * KSZ) / 8, 256>>>();        // 6528 rows

    const size_t msmem = (size_t)(2 * NBIN * SROW) * sizeof(float)
                       + (size_t)(YDIM * NBIN) * sizeof(float2);   // 183296 B
    cudaFuncSetAttribute(conv_persist_kernel,
                         cudaFuncAttributeMaxDynamicSharedMemorySize, (int)msmem);
    conv_persist_kernel<<<NCTA, NTHR, msmem>>>(x, out);
}

// round 16
// speedup vs baseline: 1.9049x; 1.1397x over previous
#include <cuda_runtime.h>
#include <cuda_pipeline.h>

// PeripheralDWConv2d, fused FFT kernel, persistent CTAs (round 16):
//  - 2 launches total: weight-spectra kernel + persistent conv kernel
//  - interleaved float2 spectra plane (LDS.64/STS.64, conflict-free)
//  - zero-padding-aware forward FFT, crop-aware pruned inverse FFT
//  - conv result S written back into the X plane (no separate S buffer)

#define KSZ 51
#define PP  13
#define RAD 25
#define NCH 128
#define NBIN 128
#define NPIMG 1024          // 8 batch-pairs * 128 channels
#define YDIM 64
#define SROW 115            // y-stride in float2 (115 mod 16 = 3 -> no conflicts)
#define NTHR 512
#define NCTA 148

__device__ float2 g_wf[NCH * KSZ * NBIN];           // conj spectra, bitrev slots

// position of quantise(a) in coords [0,1,2,4,8,16,25] for a in [0,25]
__constant__ int c_qpos[26] = {0,1,2,2,3,3,3,3,4,4,4,4,4,4,4,4,
                               5,5,5,5,5,5,5,5,5,6};

__device__ __forceinline__ float2 cmulf(float2 a, float2 b) {
    return make_float2(a.x * b.x - a.y * b.y, a.x * b.y + a.y * b.x);
}
__device__ __forceinline__ float2 cmulc(float2 a, float2 b) {  // a * conj(b)
    return make_float2(a.x * b.x + a.y * b.y, a.y * b.x - a.x * b.y);
}

// Per-thread stage twiddles tw[k] = exp(-2*pi*i*K/128), computed once.
__device__ __forceinline__ void compute_tw(float2 tw[7], int t) {
    int ks[7] = { t, t + 32, 2 * t, (t & 15) * 4, (t & 7) * 8,
                  (t & 3) * 16, (t & 1) * 32 };
#pragma unroll
    for (int i = 0; i < 7; ++i) {
        float s, c;
        sincospif(-(float)ks[i] / 64.0f, &s, &c);
        tw[i] = make_float2(c, s);
    }
}

// Forward 128-pt DIF for zero-padded input (elements 64..127 are zero).
// Thread t holds elems t,t+32 in z[0],z[1]; fills z[2],z[3].
// Output slot p = bin bitrev7(p).
__device__ __forceinline__ void fft128_fwd_pad(float2 z[4], int t, const float2 tw[7]) {
    {   // d=64 with b=0: z0'=z0, z2'=z0*w; z1'=z1, z3'=z1*w
        z[2] = cmulf(z[0], tw[0]);
        z[3] = cmulf(z[1], tw[1]);
    }
    {   // d=32
        float2 a, b;
        a = z[0]; b = z[1];
        z[0] = make_float2(a.x + b.x, a.y + b.y);
        z[1] = cmulf(make_float2(a.x - b.x, a.y - b.y), tw[2]);
        a = z[2]; b = z[3];
        z[2] = make_float2(a.x + b.x, a.y + b.y);
        z[3] = cmulf(make_float2(a.x - b.x, a.y - b.y), tw[2]);
    }
#pragma unroll
    for (int s = 0; s < 5; ++s) {      // d = 16,8,4,2,1
        int d = 16 >> s;
        float2 w = (s < 4) ? tw[3 + s] : make_float2(1.f, 0.f);
        bool hi = (t & d) != 0;
#pragma unroll
        for (int j = 0; j < 4; ++j) {
            float ox = __shfl_xor_sync(0xffffffffu, z[j].x, d);
            float oy = __shfl_xor_sync(0xffffffffu, z[j].y, d);
            if (hi) {
                float2 df = make_float2(ox - z[j].x, oy - z[j].y);
                z[j] = (d == 1) ? df : cmulf(df, w);
            } else {
                z[j] = make_float2(z[j].x + ox, z[j].y + oy);
            }
        }
    }
}

// Inverse 128-pt DIT (unnormalized), crop-aware: final butterfly computes
// only the outputs the 64-sample crop needs. On return:
//   z[0] = sample t (written to out x = t+25)
//   z[1] = sample t+32 (t<7) or sample t+96 (t>=7)
__device__ __forceinline__ void fft128_inv_pruned(float2 z[4], int t, const float2 tw[7]) {
#pragma unroll
    for (int s = 0; s < 5; ++s) {      // d = 1,2,4,8,16
        int d = 1 << s;
        float2 w = (s > 0) ? tw[7 - s] : make_float2(1.f, 0.f);  // tw[6..3]
        bool hi = (t & d) != 0;
#pragma unroll
        for (int j = 0; j < 4; ++j) {
            float ox = __shfl_xor_sync(0xffffffffu, z[j].x, d);
            float oy = __shfl_xor_sync(0xffffffffu, z[j].y, d);
            if (hi) {
                float2 vm = (d == 1) ? z[j] : cmulc(z[j], w);
                z[j] = make_float2(ox - vm.x, oy - vm.y);
            } else {
                float2 vo = (d == 1) ? make_float2(ox, oy)
                                     : cmulc(make_float2(ox, oy), w);
                z[j] = make_float2(z[j].x + vo.x, z[j].y + vo.y);
            }
        }
    }
    {   // len=64 local: w = conj(tw[2])
        float2 u, v;
        v = cmulc(z[1], tw[2]); u = z[0];
        z[0] = make_float2(u.x + v.x, u.y + v.y);
        z[1] = make_float2(u.x - v.x, u.y - v.y);
        v = cmulc(z[3], tw[2]); u = z[2];
        z[2] = make_float2(u.x + v.x, u.y + v.y);
        z[3] = make_float2(u.x - v.x, u.y - v.y);
    }
    {   // len=128 local, pruned: sample t always needed; of (t+32, t+96)
        // exactly one is needed (t<7 -> t+32, else t+96).
        float2 v0 = cmulc(z[2], tw[0]);
        z[0] = make_float2(z[0].x + v0.x, z[0].y + v0.y);
        float2 v1 = cmulc(z[3], tw[1]);
        float sgn = (t < 7) ? 1.f : -1.f;
        z[1] = make_float2(fmaf(sgn, v1.x, z[1].x), fmaf(sgn, v1.y, z[1].y));
    }
}

// Weight spectra: expand compressed weights + kpe inline, FFT, store conj.
__global__ __launch_bounds__(256)
void fft_w_kernel(const float* __restrict__ wc, const float* __restrict__ kpe) {
    int t = threadIdx.x & 31, w = threadIdx.x >> 5;
    float2 tw[7]; compute_tw(tw, t);
    int row = blockIdx.x * 8 + w;                 // c*51+dy, < 6528
    int c  = row / KSZ;
    int dy = row - c * KSZ;

    int oi = dy - RAD; int ai = oi < 0 ? -oi : oi;
    int ii = 6 + (oi < 0 ? -c_qpos[ai] : c_qpos[ai]);
    const float* wrow = wc + c * (PP * PP) + ii * PP;
    const float* krow = kpe + dy * KSZ;

    float2 z[4];
    {   // dx = t  (always < 51)
        int oj = t - RAD; int aj = oj < 0 ? -oj : oj;
        int jj = 6 + (oj < 0 ? -c_qpos[aj] : c_qpos[aj]);
        z[0] = make_float2(wrow[jj] + krow[t], 0.f);
    }
    {   // dx = t + 32 (valid if < 51)
        int dx = t + 32;
        float v = 0.f;
        if (dx < KSZ) {
            int oj = dx - RAD; int aj = oj < 0 ? -oj : oj;
            int jj = 6 + (oj < 0 ? -c_qpos[aj] : c_qpos[aj]);
            v = wrow[jj] + krow[dx];
        }
        z[1] = make_float2(v, 0.f);
    }
    fft128_fwd_pad(z, t, tw);
    float2* dst = g_wf + (size_t)row * NBIN;
    dst[t]      = make_float2(z[0].x, -z[0].y);
    dst[t + 32] = make_float2(z[1].x, -z[1].y);
    dst[t + 64] = make_float2(z[2].x, -z[2].y);
    dst[t + 96] = make_float2(z[3].x, -z[3].y);
}

// Prefetch one packed image's per-thread FFT inputs (16 floats) to registers.
__device__ __forceinline__ void prefetch_img(float pf[16], const float* __restrict__ x,
                                             int pimg, int t, int w) {
    int pb = pimg >> 7, c = pimg & 127;
    const float* i0 = x + (((size_t)(2 * pb)     * NCH + c) << 12);
    const float* i1 = x + (((size_t)(2 * pb + 1) * NCH + c) << 12);
#pragma unroll
    for (int r = 0; r < 4; ++r) {
        int y = w * 4 + r;
        pf[r * 4 + 0] = i0[y * 64 + t];
        pf[r * 4 + 1] = i0[y * 64 + t + 32];
        pf[r * 4 + 2] = i1[y * 64 + t];
        pf[r * 4 + 3] = i1[y * 64 + t + 32];
    }
}

// Persistent fused kernel: grid = NCTA, each CTA loops images b, b+148, ...
__global__ __launch_bounds__(NTHR, 1)
void conv_persist_kernel(const float* __restrict__ x, float* __restrict__ out) {
    extern __shared__ float2 smf2[];
    float2* X  = smf2;                        // 128 * SROW interleaved spectra
    float2* WS = X + NBIN * SROW;             // 51 * 128 weights

    const int tid = threadIdx.x;
    const int t   = tid & 31;                 // lane
    const int w   = tid >> 5;                 // warp 0..15

    float2 tw[7]; compute_tw(tw, t);

    // one-time halo zero: s in [0,25) u [89,115). Phases 1/3 rewrite
    // s in [25,89) densely each image, so the halo stays valid forever.
    for (int i = tid; i < NBIN * 51; i += NTHR) {
        int f = i / 51, j = i - f * 51;
        int s = (j < 25) ? j : (64 + j);      // 89..114
        X[f * SROW + s] = make_float2(0.f, 0.f);
    }

    int pimg = blockIdx.x;
    float pf[16];
    if (pimg < NPIMG) prefetch_img(pf, x, pimg, t, w);

    while (pimg < NPIMG) {
        const int pb = pimg >> 7;
        const int c  = pimg & 127;

        // stage weights via cp.async (latency hidden under phase 1)
        {
            const float2* wsrc = g_wf + (size_t)c * (KSZ * NBIN);
            for (int i = tid; i < KSZ * NBIN; i += NTHR)
                __pipeline_memcpy_async(&WS[i], &wsrc[i], sizeof(float2));
            __pipeline_commit();
        }

        // phase 1: fwd FFT 4 rows per warp from prefetched regs, scatter
#pragma unroll
        for (int r = 0; r < 4; ++r) {
            int y = w * 4 + r;                // 0..63
            float2 z[4];
            z[0] = make_float2(pf[r * 4 + 0], pf[r * 4 + 2]);
            z[1] = make_float2(pf[r * 4 + 1], pf[r * 4 + 3]);
            fft128_fwd_pad(z, t, tw);
            int s = y + RAD;
#pragma unroll
            for (int j = 0; j < 4; ++j)
                X[(t + 32 * j) * SROW + s] = z[j];
        }
        __pipeline_wait_prior(0);
        __syncthreads();                       // X + W ready

        // phase 2: prefetch next image, then y-conv
        const int pnext = pimg + NCTA;
        if (pnext < NPIMG) prefetch_img(pf, x, pnext, t, w);

        const int f  = tid & 127;
        const int y0 = (tid >> 7) * 16;        // 0,16,32,48
        float ar[16], ai[16];
        {
            const float2* xw = X + f * SROW + y0;
            const float2* wp = WS + f;

            float2 win[16];
#pragma unroll
            for (int i = 0; i < 16; ++i) { ar[i] = 0.f; ai[i] = 0.f; }
#pragma unroll
            for (int j = 0; j < 15; ++j) win[j] = xw[j];

#pragma unroll
            for (int dy = 0; dy < KSZ; ++dy) {
                win[(dy + 15) & 15] = xw[dy + 15];   // max s = 48+65 = 113 < 115
                float2 wv = wp[dy * NBIN];
#pragma unroll
                for (int i = 0; i < 16; ++i) {
                    float2 xv = win[(dy + i) & 15];
                    ar[i] = fmaf(xv.x, wv.x, fmaf(-xv.y, wv.y, ar[i]));
                    ai[i] = fmaf(xv.x, wv.y, fmaf( xv.y, wv.x, ai[i]));
                }
            }
        }
        __syncthreads();   // all X/W reads done; X data slots become S

        // phase 3: store S back into the X plane (same [f][s] slots)
        {
            float2* sp = X + f * SROW + RAD + y0;
#pragma unroll
            for (int i = 0; i < 16; ++i)
                sp[i] = make_float2(ar[i], ai[i]);
        }
        __syncthreads();

        // phase 4: inverse FFT 4 rows per warp, crop, unpack, write out
        float* o0 = out + (((size_t)(2 * pb)     * NCH + c) << 12);
        float* o1 = out + (((size_t)(2 * pb + 1) * NCH + c) << 12);
        const float scl = 1.0f / 128.0f;
#pragma unroll
        for (int r = 0; r < 4; ++r) {
            int y = w * 4 + r;
            int s = y + RAD;
            float2 z[4];
#pragma unroll
            for (int j = 0; j < 4; ++j)
                z[j] = X[(t + 32 * j) * SROW + s];
            fft128_inv_pruned(z, t, tw);
            float* p0 = o0 + y * 64;
            float* p1 = o1 + y * 64;
            p0[t + 25] = z[0].x * scl;
            p1[t + 25] = z[0].y * scl;
            int xo = (t < 7) ? (t + 57) : (t - 7);
            p0[xo] = z[1].x * scl;
            p1[xo] = z[1].y * scl;
        }
        __syncthreads();   // S reads done before next image's phase 1/W staging

        pimg = pnext;
    }
}

extern "C" void kernel_launch(void* const* d_in, const int* in_sizes, int n_in,
                              void* d_out, int out_size) {
    const float* x   = (const float*)d_in[0];   // 16*128*64*64
    const float* wc  = (const float*)d_in[1];   // 128*169
    const float* kpe = (const float*)d_in[2];   // 51*51
    float* out = (float*)d_out;

    fft_w_kernel<<<(NCH * KSZ) / 8, 256>>>(wc, kpe);   // 6528 rows

    const size_t msmem = (size_t)(NBIN * SROW + KSZ * NBIN) * sizeof(float2);
    cudaFuncSetAttribute(conv_persist_kernel,
                         cudaFuncAttributeMaxDynamicSharedMemorySize, (int)msmem);
    conv_persist_kernel<<<NCTA, NTHR, msmem>>>(x, out);
}